// round 14
// baseline (speedup 1.0000x reference)
#include <cuda_runtime.h>
#include <cuda_bf16.h>
#include <math.h>
#include <cstdint>

// Problem constants
constexpr int NB = 32;    // batch
constexpr int NL = 1024;  // La = Lb
constexpr int ND = 256;   // feature dim

// Scratch
__device__ float g_S [(size_t)NB * NL * NL];   // logits, compact [i][j]
__device__ float g_ST[(size_t)NB * NL * NL];   // logits transposed, compact [j][i]
__device__ float g_rowMax[NB * NL];
__device__ float g_rowScale[NB * NL];
__device__ float g_colMax[NB * NL];
__device__ float g_colScale[NB * NL];
__device__ int   g_idxA[NB * NL];
__device__ int   g_idxB[NB * NL];
__device__ int   g_cntA[NB];
__device__ int   g_cntB[NB];

// Compacted bf16 hi/lo copies of a, b (row = compact position), plus transposed.
__device__ __nv_bfloat16 g_Ahi [(size_t)NB * NL * ND];
__device__ __nv_bfloat16 g_Alo [(size_t)NB * NL * ND];
__device__ __nv_bfloat16 g_Bhi [(size_t)NB * NL * ND];
__device__ __nv_bfloat16 g_Blo [(size_t)NB * NL * ND];
__device__ __nv_bfloat16 g_AhiT[(size_t)NB * ND * NL];   // [d][i_compact]
__device__ __nv_bfloat16 g_AloT[(size_t)NB * ND * NL];
__device__ __nv_bfloat16 g_BhiT[(size_t)NB * ND * NL];   // [d][j_compact]
__device__ __nv_bfloat16 g_BloT[(size_t)NB * ND * NL];

// K=16 half-chunk pipeline geometry (proven in k3): rows of 24 bf16 (48B).
constexpr int RS2  = 24;
constexpr int HARR = 128 * RS2;          // 3072 bf16
constexpr uint32_t HARRB  = HARR * 2;    // 6144 B
constexpr uint32_t HSTAGE = 4 * HARRB;   // 24576 B per stage; 2 stages = 48KB

// m16n8k16 bf16 MMA, fp32 accumulate
__device__ __forceinline__ void mma_bf16(float* c, uint32_t a0, uint32_t a1,
                                         uint32_t a2, uint32_t a3,
                                         uint32_t b0, uint32_t b1) {
    asm volatile(
        "mma.sync.aligned.m16n8k16.row.col.f32.bf16.bf16.f32 "
        "{%0,%1,%2,%3}, {%4,%5,%6,%7}, {%8,%9}, {%0,%1,%2,%3};"
        : "+f"(c[0]), "+f"(c[1]), "+f"(c[2]), "+f"(c[3])
        : "r"(a0), "r"(a1), "r"(a2), "r"(a3), "r"(b0), "r"(b1));
}

__device__ __forceinline__ void ldsm_x4(uint32_t& r0, uint32_t& r1,
                                        uint32_t& r2, uint32_t& r3, uint32_t addr) {
    asm volatile("ldmatrix.sync.aligned.m8n8.x4.shared.b16 {%0,%1,%2,%3}, [%4];"
        : "=r"(r0), "=r"(r1), "=r"(r2), "=r"(r3) : "r"(addr));
}

__device__ __forceinline__ uint32_t smem_u32(const void* p) {
    uint32_t a;
    asm("{ .reg .u64 tmp; cvta.to.shared.u64 tmp, %1; cvt.u32.u64 %0, tmp; }"
        : "=r"(a) : "l"(p));
    return a;
}

__device__ __forceinline__ void cpasync16(uint32_t saddr, const void* gptr) {
    asm volatile("cp.async.cg.shared.global [%0], [%1], 16;"
        :: "r"(saddr), "l"(gptr) : "memory");
}
__device__ __forceinline__ void cpasync_commit() {
    asm volatile("cp.async.commit_group;" ::: "memory");
}
__device__ __forceinline__ void cpasync_wait0() {
    asm volatile("cp.async.wait_group 0;" ::: "memory");
}
__device__ __forceinline__ void cpasync_wait1() {
    asm volatile("cp.async.wait_group 1;" ::: "memory");
}

__device__ __forceinline__ uint32_t bf2_as_u32(__nv_bfloat162 v) {
    return *(uint32_t*)&v;
}

// ---------------------------------------------------------------------------
// K0: per-batch mask compaction (idx padded to 1024 with last valid index).
// ---------------------------------------------------------------------------
__global__ void __launch_bounds__(1024) k0_compact(const int* __restrict__ mask_a,
                                                   const int* __restrict__ mask_b) {
    const int which = blockIdx.x >> 5;
    const int bb    = blockIdx.x & 31;
    const int* m = (which ? mask_b : mask_a) + bb * NL;
    int* idx = (which ? g_idxB : g_idxA) + bb * NL;
    int* cnt = which ? g_cntB : g_cntA;
    const int t = threadIdx.x, lane = t & 31, w = t >> 5;

    int mv = (m[t] != 0);
    unsigned bal = __ballot_sync(0xffffffffu, mv);
    int pw = __popc(bal & ((1u << lane) - 1));
    __shared__ int wc[32];
    if (lane == 0) wc[w] = __popc(bal);
    __syncthreads();
    if (t < 32) {
        int v = wc[t];
#pragma unroll
        for (int o = 1; o < 32; o <<= 1) {
            int u = __shfl_up_sync(0xffffffffu, v, o);
            if (lane >= o) v += u;
        }
        wc[t] = v;
    }
    __syncthreads();
    const int base  = (w == 0) ? 0 : wc[w - 1];
    const int total = wc[31];
    if (mv) idx[base + pw] = t;
    if (t == 0) cnt[bb] = total;
    __syncthreads();
    __shared__ int lastIdx;
    if (t == 0) lastIdx = (total > 0) ? idx[total - 1] : 0;
    __syncthreads();
    if (t >= total) idx[t] = lastIdx;
}

// ---------------------------------------------------------------------------
// KZ: zero only masked output rows (replaces full memset).
// ---------------------------------------------------------------------------
__global__ void __launch_bounds__(256) k_zero(const int* __restrict__ mask_a,
                                              const int* __restrict__ mask_b,
                                              float* __restrict__ outA,
                                              float* __restrict__ outB) {
    const int which = blockIdx.z;
    const int bb    = blockIdx.y;
    const int row   = blockIdx.x * 8 + (threadIdx.x >> 5);
    const int lane  = threadIdx.x & 31;
    const int* m = which ? mask_b : mask_a;
    float* out   = which ? outB : outA;
    if (m[bb * NL + row] == 0) {
        float4 z = make_float4(0.f, 0.f, 0.f, 0.f);
        float* p = out + ((size_t)bb * NL + row) * ND;
        *(float4*)(p + lane * 4)       = z;
        *(float4*)(p + 128 + lane * 4) = z;
    }
}

// ---------------------------------------------------------------------------
// KC: gather-compact + fp32->bf16 hi/lo split + transpose.
// ---------------------------------------------------------------------------
__global__ void __launch_bounds__(256) k_conv(const float* __restrict__ a,
                                              const float* __restrict__ b) {
    const int z     = blockIdx.z;
    const int which = z >> 5;               // 0: a, 1: b
    const int bb    = z & 31;
    const int dt    = blockIdx.x * 32;
    const int rt    = blockIdx.y * 32;
    const int cnt   = which ? g_cntB[bb] : g_cntA[bb];
    if (rt >= ((cnt + 127) & ~127)) return;
    const float* src = which ? b : a;
    const int* idx   = (which ? g_idxB : g_idxA) + bb * NL;
    __nv_bfloat16* oH  = which ? g_Bhi  : g_Ahi;
    __nv_bfloat16* oL  = which ? g_Blo  : g_Alo;
    __nv_bfloat16* oHT = which ? g_BhiT : g_AhiT;
    __nv_bfloat16* oLT = which ? g_BloT : g_AloT;

    const int tx = threadIdx.x & 31;
    const int ty = threadIdx.x >> 5;
    __shared__ float tile[32][33];

#pragma unroll
    for (int rr = 0; rr < 4; rr++) {
        int rl = ty + 8 * rr;
        int grow = idx[rt + rl];
        float v = src[((size_t)bb * NL + grow) * ND + dt + tx];
        tile[rl][tx] = v;
        __nv_bfloat16 h = __float2bfloat16(v);
        __nv_bfloat16 l = __float2bfloat16(v - __bfloat162float(h));
        size_t o = ((size_t)bb * NL + rt + rl) * ND + dt + tx;
        oH[o] = h; oL[o] = l;
    }
    __syncthreads();
#pragma unroll
    for (int rr = 0; rr < 4; rr++) {
        int dl = ty + 8 * rr;
        float v = tile[tx][dl];
        __nv_bfloat16 h = __float2bfloat16(v);
        __nv_bfloat16 l = __float2bfloat16(v - __bfloat162float(h));
        size_t o = ((size_t)bb * ND + dt + dl) * NL + rt + tx;
        oHT[o] = h; oLT[o] = l;
    }
}

// ---------------------------------------------------------------------------
// K1 (k3-isomorphic): S = a_c @ b_c^T, 3-term bf16 mma.sync.
// K=16 half-chunk double buffer (48KB static): stage = [Ah|Al|Bh|Bl].
// B via cp.async (2 arrays); A via LDG->reg (under MMA)->STS. Writes g_S+g_ST.
// ---------------------------------------------------------------------------
__global__ void __launch_bounds__(256, 2) k1_mma() {
    const int bb  = blockIdx.z;
    const int ib0 = blockIdx.y * 128;
    const int jb0 = blockIdx.x * 128;
    const int na  = g_cntA[bb];
    const int nb  = g_cntB[bb];
    if (ib0 >= na || jb0 >= nb) return;

    __shared__ __align__(16) __nv_bfloat16 smh[2 * 4 * HARR];  // 49152 B
    const uint32_t base_u = smem_u32(smh);
    float* tbuf = (float*)smh;  // reused post-MMA

    const int t    = threadIdx.x;
    const int lane = t & 31;
    const int wid  = t >> 5;
    const int wm   = wid >> 1;   // 0..3
    const int wn   = wid & 1;    // 0..1
    const int gq   = lane >> 2;

    const int lrow = (lane & 7) + ((lane >> 3) & 1) * 8;
    const int lcol = (lane >> 4) * 8;

    float c[2][8][4];
#pragma unroll
    for (int mf = 0; mf < 2; mf++)
#pragma unroll
        for (int nf = 0; nf < 8; nf++)
#pragma unroll
            for (int v = 0; v < 4; v++) c[mf][nf][v] = 0.f;

    const size_t aBase = ((size_t)bb * NL + ib0) * ND;
    const size_t bBase = ((size_t)bb * NL + jb0) * ND;
    const int prow = t >> 1;            // 0..127 (both cp.async B and LDG A)
    const int pc8  = (t & 1) * 8;       // bf16 col within half-chunk

    auto issueB = [&](int ci, int s) {
        const uint32_t st = base_u + (uint32_t)s * HSTAGE + 2 * HARRB;
        size_t go = bBase + (size_t)prow * ND + ci * 16 + pc8;
        uint32_t so = st + (uint32_t)((prow * RS2 + pc8) * 2);
        cpasync16(so,         &g_Bhi[go]);
        cpasync16(so + HARRB, &g_Blo[go]);
        cpasync_commit();
    };

    uint4 ah, al;
    auto loadA = [&](int ci) {
        size_t go = aBase + (size_t)prow * ND + ci * 16 + pc8;
        ah = *(const uint4*)&g_Ahi[go];
        al = *(const uint4*)&g_Alo[go];
    };
    auto storeA = [&](int s) {
        __nv_bfloat16* sAh = smh + s * (4 * HARR);
        __nv_bfloat16* sAl = sAh + HARR;
        int so = prow * RS2 + pc8;
        *(uint4*)&sAh[so] = ah;
        *(uint4*)&sAl[so] = al;
    };

    constexpr int NCH = ND / 16;  // 16
    // prologue
    issueB(0, 0);
    issueB(1, 1);
    loadA(0);
    storeA(0);

#pragma unroll 1
    for (int i = 0; i < NCH; i++) {
        if (i == NCH - 1) cpasync_wait0(); else cpasync_wait1();
        __syncthreads();
        const bool more = (i + 1 < NCH);
        if (more) loadA(i + 1);  // LDG in flight under the MMAs
        const uint32_t st = base_u + (uint32_t)(i & 1) * HSTAGE;
#pragma unroll
        for (int term = 0; term < 3; term++) {
            const uint32_t au = st + ((term == 2) ? HARRB : 0u);
            const uint32_t bu = st + 2 * HARRB + ((term == 1) ? HARRB : 0u);
            uint32_t b0[8], b1[8];
#pragma unroll
            for (int nfp = 0; nfp < 4; nfp++) {
                uint32_t addr = bu +
                    (uint32_t)(((wn * 64 + nfp * 16 + lrow) * RS2 + lcol) * 2);
                ldsm_x4(b0[2 * nfp], b0[2 * nfp + 1], b1[2 * nfp], b1[2 * nfp + 1], addr);
            }
#pragma unroll
            for (int mf = 0; mf < 2; mf++) {
                uint32_t a0, a1, a2, a3;
                uint32_t addrA = au +
                    (uint32_t)(((wm * 32 + mf * 16 + lrow) * RS2 + lcol) * 2);
                ldsm_x4(a0, a1, a2, a3, addrA);
#pragma unroll
                for (int nf = 0; nf < 8; nf++)
                    mma_bf16(c[mf][nf], a0, a1, a2, a3, b0[nf], b1[nf]);
            }
        }
        __syncthreads();
        if (more) storeA((i + 1) & 1);
        if (i + 2 < NCH) issueB(i + 2, i & 1);
    }

    // ---- epilogue 1: direct store to g_S
#pragma unroll
    for (int mf = 0; mf < 2; mf++)
#pragma unroll
        for (int nf = 0; nf < 8; nf++) {
            int r  = ib0 + wm * 32 + mf * 16 + gq;
            int jj = jb0 + wn * 64 + nf * 8 + 2 * (lane & 3);
            *(float2*)&g_S[((size_t)(bb * NL) + r) * NL + jj] =
                make_float2(c[mf][nf][0], c[mf][nf][1]);
            *(float2*)&g_S[((size_t)(bb * NL) + r + 8) * NL + jj] =
                make_float2(c[mf][nf][2], c[mf][nf][3]);
        }

    // ---- epilogue 2: transpose to g_ST via smem, 4 passes of 32 j-cols
#pragma unroll 1
    for (int p = 0; p < 4; p++) {
        __syncthreads();
        if (wn == (p >> 1)) {
            int nfb = (p & 1) * 4;
#pragma unroll
            for (int mf = 0; mf < 2; mf++)
#pragma unroll
                for (int nfo = 0; nfo < 4; nfo++) {
                    int nf = nfb + nfo;
                    int jl = wn * 64 + nf * 8 + 2 * (lane & 3) - p * 32;
                    int il = wm * 32 + mf * 16 + gq;
                    tbuf[jl * 132 + il]           = c[mf][nf][0];
                    tbuf[(jl + 1) * 132 + il]     = c[mf][nf][1];
                    tbuf[jl * 132 + il + 8]       = c[mf][nf][2];
                    tbuf[(jl + 1) * 132 + il + 8] = c[mf][nf][3];
                }
        }
        __syncthreads();
#pragma unroll
        for (int q = 0; q < 4; q++) {
            int id  = t + 256 * q;
            int jl  = id >> 5;
            int il4 = (id & 31) * 4;
            int gj  = jb0 + p * 32 + jl;
            *(float4*)&g_ST[((size_t)(bb * NL) + gj) * NL + ib0 + il4] =
                *(float4*)&tbuf[jl * 132 + il4];
        }
    }
}

// ---------------------------------------------------------------------------
// K2: softmax stats; both orientations in ONE launch (which = blockIdx.y).
// ---------------------------------------------------------------------------
__global__ void __launch_bounds__(256) k2_stats() {
    const int which = blockIdx.y;
    const int warp  = threadIdx.x >> 5;
    const int lane  = threadIdx.x & 31;
    const int rowid = blockIdx.x * 8 + warp;
    const int bb    = rowid >> 10;
    const int r     = rowid & (NL - 1);
    const int cntM  = which ? g_cntB[bb] : g_cntA[bb];
    const int cntK  = which ? g_cntA[bb] : g_cntB[bb];
    if (r >= cntM) return;
    const float* Srow = (which ? g_ST : g_S) + (size_t)rowid * NL;
    float* oMax = which ? g_colMax : g_rowMax;
    float* oSc  = which ? g_colScale : g_rowScale;

    const int k4 = cntK & ~3;
    float m = -INFINITY;
    for (int j = lane * 4; j < k4; j += 128) {
        float4 v = *(const float4*)(Srow + j);
        m = fmaxf(m, fmaxf(fmaxf(v.x, v.y), fmaxf(v.z, v.w)));
    }
    for (int j = k4 + lane; j < cntK; j += 32) m = fmaxf(m, Srow[j]);
#pragma unroll
    for (int o = 16; o > 0; o >>= 1) m = fmaxf(m, __shfl_xor_sync(0xffffffffu, m, o));

    float s = 0.f;
    if (m != -INFINITY) {
        for (int j = lane * 4; j < k4; j += 128) {
            float4 v = *(const float4*)(Srow + j);
            s += __expf(v.x - m) + __expf(v.y - m) + __expf(v.z - m) + __expf(v.w - m);
        }
        for (int j = k4 + lane; j < cntK; j += 32) s += __expf(Srow[j] - m);
    }
#pragma unroll
    for (int o = 16; o > 0; o >>= 1) s += __shfl_xor_sync(0xffffffffu, s, o);

    if (lane == 0) {
        if (m == -INFINITY) { oMax[rowid] = 0.f; oSc[rowid] = 0.f; }
        else                { oMax[rowid] = m;   oSc[rowid] = 1.f / s; }
    }
}

// ---------------------------------------------------------------------------
// K3 (R10/R11 version): attended = softmax-weights @ values; both directions.
// K=16 half-chunk double buffer (static 48KB): stage = [Wh|Wl|Vh|Vl].
// ---------------------------------------------------------------------------
__global__ void __launch_bounds__(256, 2) k3_mma(float* __restrict__ outA,
                                                 float* __restrict__ outB) {
    const int z     = blockIdx.z;
    const int which = z >> 5;
    const int bb    = z & 31;
    const int m0    = blockIdx.y * 128;
    const int db0   = blockIdx.x * 128;
    const int cntM  = which ? g_cntB[bb] : g_cntA[bb];
    const int cntK  = which ? g_cntA[bb] : g_cntB[bb];
    if (m0 >= cntM) return;
    float* out = which ? outB : outA;

    const float* Sarr = which ? g_ST : g_S;
    const float* stM  = which ? g_colMax : g_rowMax;
    const float* stSc = which ? g_colScale : g_rowScale;
    const __nv_bfloat16* VhT = which ? g_AhiT : g_BhiT;
    const __nv_bfloat16* VlT = which ? g_AloT : g_BloT;
    const int* idxOut = (which ? g_idxB : g_idxA) + bb * NL;

    __shared__ __align__(16) __nv_bfloat16 smh[2 * 4 * HARR];  // 49152 B
    const uint32_t base_u = smem_u32(smh);

    const int t    = threadIdx.x;
    const int lane = t & 31;
    const int wid  = t >> 5;
    const int wm   = wid >> 1;
    const int wn   = wid & 1;
    const int gq   = lane >> 2;

    const int lrow = (lane & 7) + ((lane >> 3) & 1) * 8;
    const int lcol = (lane >> 4) * 8;

    const int wrow = t >> 1;
    const int wcol = (t & 1) * 8;
    const float mreg = stM[bb * NL + m0 + wrow];

    const int er = wm * 32 + gq;
    const float esc0 = stSc[bb * NL + m0 + er];
    const float esc1 = stSc[bb * NL + m0 + er + 8];
    const float esc2 = stSc[bb * NL + m0 + er + 16];
    const float esc3 = stSc[bb * NL + m0 + er + 24];
    const int eid0 = idxOut[m0 + er];
    const int eid1 = idxOut[m0 + er + 8];
    const int eid2 = idxOut[m0 + er + 16];
    const int eid3 = idxOut[m0 + er + 24];

    float c[2][8][4];
#pragma unroll
    for (int mf = 0; mf < 2; mf++)
#pragma unroll
        for (int nf = 0; nf < 8; nf++)
#pragma unroll
            for (int v = 0; v < 4; v++) c[mf][nf][v] = 0.f;

    const size_t sBase = ((size_t)bb * NL + m0) * NL;
    const size_t vBase = ((size_t)bb * ND + db0) * NL;
    const int nch = ((cntK + 15) & ~15) / 16;
    const int cprow = t >> 1;
    const int cpc8  = (t & 1) * 8;

    auto issueV = [&](int ci, int s) {
        const uint32_t st = base_u + (uint32_t)s * HSTAGE + 2 * HARRB;
        size_t go = vBase + (size_t)cprow * NL + ci * 16 + cpc8;
        uint32_t so = st + (uint32_t)((cprow * RS2 + cpc8) * 2);
        cpasync16(so,         &VhT[go]);
        cpasync16(so + HARRB, &VlT[go]);
        cpasync_commit();
    };

    float4 s0, s1;
    auto loadS = [&](int ci) {
        const float* p = &Sarr[sBase + (size_t)wrow * NL + ci * 16 + wcol];
        s0 = *(const float4*)p;
        s1 = *(const float4*)(p + 4);
    };
    auto storeW = [&](int ci, int s) {
        __nv_bfloat16* sWh = smh + s * (4 * HARR);
        __nv_bfloat16* sWl = sWh + HARR;
        int cb = ci * 16 + wcol;
        float w0 = (cb + 0 < cntK) ? __expf(s0.x - mreg) : 0.f;
        float w1 = (cb + 1 < cntK) ? __expf(s0.y - mreg) : 0.f;
        float w2 = (cb + 2 < cntK) ? __expf(s0.z - mreg) : 0.f;
        float w3 = (cb + 3 < cntK) ? __expf(s0.w - mreg) : 0.f;
        float w4 = (cb + 4 < cntK) ? __expf(s1.x - mreg) : 0.f;
        float w5 = (cb + 5 < cntK) ? __expf(s1.y - mreg) : 0.f;
        float w6 = (cb + 6 < cntK) ? __expf(s1.z - mreg) : 0.f;
        float w7 = (cb + 7 < cntK) ? __expf(s1.w - mreg) : 0.f;
        __nv_bfloat162 h01 = __floats2bfloat162_rn(w0, w1);
        __nv_bfloat162 h23 = __floats2bfloat162_rn(w2, w3);
        __nv_bfloat162 h45 = __floats2bfloat162_rn(w4, w5);
        __nv_bfloat162 h67 = __floats2bfloat162_rn(w6, w7);
        __nv_bfloat162 l01 = __floats2bfloat162_rn(
            w0 - __bfloat162float(__low2bfloat16(h01)),
            w1 - __bfloat162float(__high2bfloat16(h01)));
        __nv_bfloat162 l23 = __floats2bfloat162_rn(
            w2 - __bfloat162float(__low2bfloat16(h23)),
            w3 - __bfloat162float(__high2bfloat16(h23)));
        __nv_bfloat162 l45 = __floats2bfloat162_rn(
            w4 - __bfloat162float(__low2bfloat16(h45)),
            w5 - __bfloat162float(__high2bfloat16(h45)));
        __nv_bfloat162 l67 = __floats2bfloat162_rn(
            w6 - __bfloat162float(__low2bfloat16(h67)),
            w7 - __bfloat162float(__high2bfloat16(h67)));
        int so = wrow * RS2 + wcol;
        *(uint4*)&sWh[so] = make_uint4(bf2_as_u32(h01), bf2_as_u32(h23),
                                       bf2_as_u32(h45), bf2_as_u32(h67));
        *(uint4*)&sWl[so] = make_uint4(bf2_as_u32(l01), bf2_as_u32(l23),
                                       bf2_as_u32(l45), bf2_as_u32(l67));
    };

    // prologue
    issueV(0, 0);
    if (nch > 1) issueV(1, 1);
    loadS(0);
    storeW(0, 0);

#pragma unroll 1
    for (int i = 0; i < nch; i++) {
        if (i == nch - 1) cpasync_wait0(); else cpasync_wait1();
        __syncthreads();
        const bool more = (i + 1 < nch);
        if (more) loadS(i + 1);  // 8 regs, LDG in flight under the MMAs
        const uint32_t st = base_u + (uint32_t)(i & 1) * HSTAGE;
#pragma unroll
        for (int term = 0; term < 3; term++) {
            const uint32_t au = st + ((term == 2) ? HARRB : 0u);
            const uint32_t bu = st + 2 * HARRB + ((term == 1) ? HARRB : 0u);
            uint32_t b0[8], b1[8];
#pragma unroll
            for (int nfp = 0; nfp < 4; nfp++) {
                uint32_t addr = bu +
                    (uint32_t)(((wn * 64 + nfp * 16 + lrow) * RS2 + lcol) * 2);
                ldsm_x4(b0[2 * nfp], b0[2 * nfp + 1], b1[2 * nfp], b1[2 * nfp + 1], addr);
            }
#pragma unroll
            for (int mf = 0; mf < 2; mf++) {
                uint32_t a0, a1, a2, a3;
                uint32_t addrA = au +
                    (uint32_t)(((wm * 32 + mf * 16 + lrow) * RS2 + lcol) * 2);
                ldsm_x4(a0, a1, a2, a3, addrA);
#pragma unroll
                for (int nf = 0; nf < 8; nf++)
                    mma_bf16(c[mf][nf], a0, a1, a2, a3, b0[nf], b1[nf]);
            }
        }
        __syncthreads();
        if (more) storeW(i + 1, (i + 1) & 1);
        if (i + 2 < nch) issueV(i + 2, i & 1);
    }

    // ---- epilogue: scale + scatter (stats from registers)
#pragma unroll
    for (int mf = 0; mf < 2; mf++) {
        int rl = wm * 32 + mf * 16 + gq;
        float scA = mf ? esc2 : esc0;
        float scB = mf ? esc3 : esc1;
        int   idA = mf ? eid2 : eid0;
        int   idB = mf ? eid3 : eid1;
#pragma unroll
        for (int nf = 0; nf < 8; nf++) {
            int jj = db0 + wn * 64 + nf * 8 + 2 * (lane & 3);
            if (m0 + rl < cntM) {
                *(float2*)&out[((size_t)(bb * NL) + idA) * ND + jj] =
                    make_float2(c[mf][nf][0] * scA, c[mf][nf][1] * scA);
            }
            if (m0 + rl + 8 < cntM) {
                *(float2*)&out[((size_t)(bb * NL) + idB) * ND + jj] =
                    make_float2(c[mf][nf][2] * scB, c[mf][nf][3] * scB);
            }
        }
    }
}

// ---------------------------------------------------------------------------
extern "C" void kernel_launch(void* const* d_in, const int* in_sizes, int n_in,
                              void* d_out, int out_size) {
    const float* a      = (const float*)d_in[0];
    const float* b      = (const float*)d_in[1];
    const int*   mask_a = (const int*)d_in[2];
    const int*   mask_b = (const int*)d_in[3];
    float* outA = (float*)d_out;
    float* outB = outA + (size_t)NB * NL * ND;

    k0_compact<<<64, 1024>>>(mask_a, mask_b);
    k_zero<<<dim3(NL / 8, NB, 2), 256>>>(mask_a, mask_b, outA, outB);
    k_conv<<<dim3(8, 32, 64), 256>>>(a, b);
    k1_mma<<<dim3(8, 8, NB), 256>>>();
    k2_stats<<<dim3(NB * NL / 8, 2), 256>>>();
    k3_mma<<<dim3(2, 8, 64), 256>>>(outA, outB);
}

// round 15
// speedup vs baseline: 1.3027x; 1.3027x over previous
#include <cuda_runtime.h>
#include <cuda_bf16.h>
#include <math.h>
#include <cstdint>

// Problem constants
constexpr int NB = 32;    // batch
constexpr int NL = 1024;  // La = Lb
constexpr int ND = 256;   // feature dim

// Scratch
__device__ float g_S [(size_t)NB * NL * NL];   // logits, compact [i][j]
__device__ float g_ST[(size_t)NB * NL * NL];   // logits transposed, compact [j][i]
__device__ float g_rowMax[NB * NL];
__device__ float g_rowScale[NB * NL];
__device__ float g_colMax[NB * NL];
__device__ float g_colScale[NB * NL];
__device__ int   g_idxA[NB * NL];
__device__ int   g_idxB[NB * NL];
__device__ int   g_cntA[NB];
__device__ int   g_cntB[NB];

// Compacted bf16 hi/lo copies of a, b (row = compact position), plus transposed.
__device__ __nv_bfloat16 g_Ahi [(size_t)NB * NL * ND];
__device__ __nv_bfloat16 g_Alo [(size_t)NB * NL * ND];
__device__ __nv_bfloat16 g_Bhi [(size_t)NB * NL * ND];
__device__ __nv_bfloat16 g_Blo [(size_t)NB * NL * ND];
__device__ __nv_bfloat16 g_AhiT[(size_t)NB * ND * NL];   // [d][i_compact]
__device__ __nv_bfloat16 g_AloT[(size_t)NB * ND * NL];
__device__ __nv_bfloat16 g_BhiT[(size_t)NB * ND * NL];   // [d][j_compact]
__device__ __nv_bfloat16 g_BloT[(size_t)NB * ND * NL];

// k1 geometry (R8/R11): K=32 chunks, rows of 40 bf16 (80B), single buffer.
constexpr int RS = 40;
// k3 geometry (R10/R11): K=16 half-chunks, rows of 24 bf16 (48B), double buffer.
constexpr int RS2  = 24;
constexpr int HARR = 128 * RS2;          // 3072 bf16
constexpr uint32_t HARRB  = HARR * 2;    // 6144 B
constexpr uint32_t HSTAGE = 4 * HARRB;   // 24576 B per stage

// m16n8k16 bf16 MMA, fp32 accumulate
__device__ __forceinline__ void mma_bf16(float* c, uint32_t a0, uint32_t a1,
                                         uint32_t a2, uint32_t a3,
                                         uint32_t b0, uint32_t b1) {
    asm volatile(
        "mma.sync.aligned.m16n8k16.row.col.f32.bf16.bf16.f32 "
        "{%0,%1,%2,%3}, {%4,%5,%6,%7}, {%8,%9}, {%0,%1,%2,%3};"
        : "+f"(c[0]), "+f"(c[1]), "+f"(c[2]), "+f"(c[3])
        : "r"(a0), "r"(a1), "r"(a2), "r"(a3), "r"(b0), "r"(b1));
}

__device__ __forceinline__ void ldsm_x4(uint32_t& r0, uint32_t& r1,
                                        uint32_t& r2, uint32_t& r3, uint32_t addr) {
    asm volatile("ldmatrix.sync.aligned.m8n8.x4.shared.b16 {%0,%1,%2,%3}, [%4];"
        : "=r"(r0), "=r"(r1), "=r"(r2), "=r"(r3) : "r"(addr));
}

__device__ __forceinline__ uint32_t smem_u32(const void* p) {
    uint32_t a;
    asm("{ .reg .u64 tmp; cvta.to.shared.u64 tmp, %1; cvt.u32.u64 %0, tmp; }"
        : "=r"(a) : "l"(p));
    return a;
}

__device__ __forceinline__ void cpasync16(uint32_t saddr, const void* gptr) {
    asm volatile("cp.async.cg.shared.global [%0], [%1], 16;"
        :: "r"(saddr), "l"(gptr) : "memory");
}
__device__ __forceinline__ void cpasync_commit() {
    asm volatile("cp.async.commit_group;" ::: "memory");
}
__device__ __forceinline__ void cpasync_wait0() {
    asm volatile("cp.async.wait_group 0;" ::: "memory");
}
__device__ __forceinline__ void cpasync_wait1() {
    asm volatile("cp.async.wait_group 1;" ::: "memory");
}

__device__ __forceinline__ uint32_t bf2_as_u32(__nv_bfloat162 v) {
    return *(uint32_t*)&v;
}

// ---------------------------------------------------------------------------
// K0: per-batch mask compaction (idx padded to 1024 with last valid index).
// ---------------------------------------------------------------------------
__global__ void __launch_bounds__(1024) k0_compact(const int* __restrict__ mask_a,
                                                   const int* __restrict__ mask_b) {
    const int which = blockIdx.x >> 5;
    const int bb    = blockIdx.x & 31;
    const int* m = (which ? mask_b : mask_a) + bb * NL;
    int* idx = (which ? g_idxB : g_idxA) + bb * NL;
    int* cnt = which ? g_cntB : g_cntA;
    const int t = threadIdx.x, lane = t & 31, w = t >> 5;

    int mv = (m[t] != 0);
    unsigned bal = __ballot_sync(0xffffffffu, mv);
    int pw = __popc(bal & ((1u << lane) - 1));
    __shared__ int wc[32];
    if (lane == 0) wc[w] = __popc(bal);
    __syncthreads();
    if (t < 32) {
        int v = wc[t];
#pragma unroll
        for (int o = 1; o < 32; o <<= 1) {
            int u = __shfl_up_sync(0xffffffffu, v, o);
            if (lane >= o) v += u;
        }
        wc[t] = v;
    }
    __syncthreads();
    const int base  = (w == 0) ? 0 : wc[w - 1];
    const int total = wc[31];
    if (mv) idx[base + pw] = t;
    if (t == 0) cnt[bb] = total;
    __syncthreads();
    __shared__ int lastIdx;
    if (t == 0) lastIdx = (total > 0) ? idx[total - 1] : 0;
    __syncthreads();
    if (t >= total) idx[t] = lastIdx;
}

// ---------------------------------------------------------------------------
// KZ: zero only masked output rows (replaces full memset).
// ---------------------------------------------------------------------------
__global__ void __launch_bounds__(256) k_zero(const int* __restrict__ mask_a,
                                              const int* __restrict__ mask_b,
                                              float* __restrict__ outA,
                                              float* __restrict__ outB) {
    const int which = blockIdx.z;
    const int bb    = blockIdx.y;
    const int row   = blockIdx.x * 8 + (threadIdx.x >> 5);
    const int lane  = threadIdx.x & 31;
    const int* m = which ? mask_b : mask_a;
    float* out   = which ? outB : outA;
    if (m[bb * NL + row] == 0) {
        float4 z = make_float4(0.f, 0.f, 0.f, 0.f);
        float* p = out + ((size_t)bb * NL + row) * ND;
        *(float4*)(p + lane * 4)       = z;
        *(float4*)(p + 128 + lane * 4) = z;
    }
}

// ---------------------------------------------------------------------------
// KC: gather-compact + fp32->bf16 hi/lo split + transpose.
// ---------------------------------------------------------------------------
__global__ void __launch_bounds__(256) k_conv(const float* __restrict__ a,
                                              const float* __restrict__ b) {
    const int z     = blockIdx.z;
    const int which = z >> 5;               // 0: a, 1: b
    const int bb    = z & 31;
    const int dt    = blockIdx.x * 32;
    const int rt    = blockIdx.y * 32;
    const int cnt   = which ? g_cntB[bb] : g_cntA[bb];
    if (rt >= ((cnt + 127) & ~127)) return;
    const float* src = which ? b : a;
    const int* idx   = (which ? g_idxB : g_idxA) + bb * NL;
    __nv_bfloat16* oH  = which ? g_Bhi  : g_Ahi;
    __nv_bfloat16* oL  = which ? g_Blo  : g_Alo;
    __nv_bfloat16* oHT = which ? g_BhiT : g_AhiT;
    __nv_bfloat16* oLT = which ? g_BloT : g_AloT;

    const int tx = threadIdx.x & 31;
    const int ty = threadIdx.x >> 5;
    __shared__ float tile[32][33];

#pragma unroll
    for (int rr = 0; rr < 4; rr++) {
        int rl = ty + 8 * rr;
        int grow = idx[rt + rl];
        float v = src[((size_t)bb * NL + grow) * ND + dt + tx];
        tile[rl][tx] = v;
        __nv_bfloat16 h = __float2bfloat16(v);
        __nv_bfloat16 l = __float2bfloat16(v - __bfloat162float(h));
        size_t o = ((size_t)bb * NL + rt + rl) * ND + dt + tx;
        oH[o] = h; oL[o] = l;
    }
    __syncthreads();
#pragma unroll
    for (int rr = 0; rr < 4; rr++) {
        int dl = ty + 8 * rr;
        float v = tile[tx][dl];
        __nv_bfloat16 h = __float2bfloat16(v);
        __nv_bfloat16 l = __float2bfloat16(v - __bfloat162float(h));
        size_t o = ((size_t)bb * ND + dt + dl) * NL + rt + tx;
        oHT[o] = h; oLT[o] = l;
    }
}

// ---------------------------------------------------------------------------
// K1 (R11 version): S = a_c @ b_c^T, 3-term bf16 mma.sync, ldmatrix,
// K=32 chunks, single buffer + cp.async. Writes g_S AND g_ST.
// Transpose epilogue: 2 passes of 64 j-cols (tbuf 64x132 fp32 = 33.8KB).
// ---------------------------------------------------------------------------
__global__ void __launch_bounds__(256, 2) k1_mma() {
    const int bb  = blockIdx.z;
    const int ib0 = blockIdx.y * 128;
    const int jb0 = blockIdx.x * 128;
    const int na  = g_cntA[bb];
    const int nb  = g_cntB[bb];
    if (ib0 >= na || jb0 >= nb) return;

    __shared__ __align__(16) __nv_bfloat16 sm[4 * 128 * RS];  // 40960B
    __nv_bfloat16* sAh = sm;
    __nv_bfloat16* sAl = sAh + 128 * RS;
    __nv_bfloat16* sBh = sAl + 128 * RS;
    __nv_bfloat16* sBl = sBh + 128 * RS;
    float* tbuf = (float*)sm;  // reused post-MMA (64*132*4 = 33792 <= 40960)

    const int t    = threadIdx.x;
    const int lane = t & 31;
    const int wid  = t >> 5;
    const int wm   = wid >> 1;   // 0..3
    const int wn   = wid & 1;    // 0..1
    const int gq   = lane >> 2;

    const int lrow = (lane & 7) + ((lane >> 3) & 1) * 8;
    const int lcol = (lane >> 4) * 8;

    const uint32_t sAh_u = smem_u32(sAh), sAl_u = smem_u32(sAl);
    const uint32_t sBh_u = smem_u32(sBh), sBl_u = smem_u32(sBl);

    float c[2][8][4];
#pragma unroll
    for (int mf = 0; mf < 2; mf++)
#pragma unroll
        for (int nf = 0; nf < 8; nf++)
#pragma unroll
            for (int v = 0; v < 4; v++) c[mf][nf][v] = 0.f;

    const size_t aBase = ((size_t)bb * NL + ib0) * ND;
    const size_t bBase = ((size_t)bb * NL + jb0) * ND;
    const int cprow0 = t >> 2;          // +64 per pass
    const int cpc8   = (t & 3) * 8;     // bf16 col (8 per 16B)

    // issue chunk 0
#pragma unroll
    for (int p = 0; p < 2; p++) {
        int row = cprow0 + 64 * p;
        size_t go = (size_t)row * ND + cpc8;
        uint32_t so = (uint32_t)((row * RS + cpc8) * 2);
        cpasync16(sAh_u + so, &g_Ahi[aBase + go]);
        cpasync16(sAl_u + so, &g_Alo[aBase + go]);
        cpasync16(sBh_u + so, &g_Bhi[bBase + go]);
        cpasync16(sBl_u + so, &g_Blo[bBase + go]);
    }
    cpasync_commit();

#pragma unroll 1
    for (int kc = 0; kc < ND; kc += 32) {
        cpasync_wait0();
        __syncthreads();
#pragma unroll
        for (int term = 0; term < 3; term++) {
            const uint32_t au = (term == 2) ? sAl_u : sAh_u;
            const uint32_t bu = (term == 1) ? sBl_u : sBh_u;
#pragma unroll
            for (int k0 = 0; k0 < 32; k0 += 16) {
                uint32_t b0[8], b1[8];
#pragma unroll
                for (int nfp = 0; nfp < 4; nfp++) {
                    uint32_t addr = bu +
                        (uint32_t)(((wn * 64 + nfp * 16 + lrow) * RS + k0 + lcol) * 2);
                    ldsm_x4(b0[2 * nfp], b0[2 * nfp + 1], b1[2 * nfp], b1[2 * nfp + 1], addr);
                }
#pragma unroll
                for (int mf = 0; mf < 2; mf++) {
                    uint32_t a0, a1, a2, a3;
                    uint32_t addrA = au +
                        (uint32_t)(((wm * 32 + mf * 16 + lrow) * RS + k0 + lcol) * 2);
                    ldsm_x4(a0, a1, a2, a3, addrA);
#pragma unroll
                    for (int nf = 0; nf < 8; nf++)
                        mma_bf16(c[mf][nf], a0, a1, a2, a3, b0[nf], b1[nf]);
                }
            }
        }
        __syncthreads();
        if (kc + 32 < ND) {
#pragma unroll
            for (int p = 0; p < 2; p++) {
                int row = cprow0 + 64 * p;
                size_t go = (size_t)row * ND + kc + 32 + cpc8;
                uint32_t so = (uint32_t)((row * RS + cpc8) * 2);
                cpasync16(sAh_u + so, &g_Ahi[aBase + go]);
                cpasync16(sAl_u + so, &g_Alo[aBase + go]);
                cpasync16(sBh_u + so, &g_Bhi[bBase + go]);
                cpasync16(sBl_u + so, &g_Blo[bBase + go]);
            }
            cpasync_commit();
        }
    }

    // ---- epilogue 1: direct store to g_S
#pragma unroll
    for (int mf = 0; mf < 2; mf++)
#pragma unroll
        for (int nf = 0; nf < 8; nf++) {
            int r  = ib0 + wm * 32 + mf * 16 + gq;
            int jj = jb0 + wn * 64 + nf * 8 + 2 * (lane & 3);
            *(float2*)&g_S[((size_t)(bb * NL) + r) * NL + jj] =
                make_float2(c[mf][nf][0], c[mf][nf][1]);
            *(float2*)&g_S[((size_t)(bb * NL) + r + 8) * NL + jj] =
                make_float2(c[mf][nf][2], c[mf][nf][3]);
        }

    // ---- epilogue 2: transpose to g_ST via smem, 2 passes of 64 j-cols
#pragma unroll 1
    for (int p = 0; p < 2; p++) {
        __syncthreads();
        if (wn == p) {
#pragma unroll
            for (int mf = 0; mf < 2; mf++)
#pragma unroll
                for (int nf = 0; nf < 8; nf++) {
                    int jl = nf * 8 + 2 * (lane & 3);        // 0..63 within pass
                    int il = wm * 32 + mf * 16 + gq;
                    tbuf[jl * 132 + il]           = c[mf][nf][0];
                    tbuf[(jl + 1) * 132 + il]     = c[mf][nf][1];
                    tbuf[jl * 132 + il + 8]       = c[mf][nf][2];
                    tbuf[(jl + 1) * 132 + il + 8] = c[mf][nf][3];
                }
        }
        __syncthreads();
#pragma unroll
        for (int q = 0; q < 8; q++) {
            int id  = t + 256 * q;      // 0..2047: 64 j-rows x 32 float4
            int jl  = id >> 5;
            int il4 = (id & 31) * 4;
            int gj  = jb0 + p * 64 + jl;
            *(float4*)&g_ST[((size_t)(bb * NL) + gj) * NL + ib0 + il4] =
                *(float4*)&tbuf[jl * 132 + il4];
        }
    }
}

// ---------------------------------------------------------------------------
// K2: softmax stats; both orientations in ONE launch (which = blockIdx.y).
// ---------------------------------------------------------------------------
__global__ void __launch_bounds__(256) k2_stats() {
    const int which = blockIdx.y;
    const int warp  = threadIdx.x >> 5;
    const int lane  = threadIdx.x & 31;
    const int rowid = blockIdx.x * 8 + warp;
    const int bb    = rowid >> 10;
    const int r     = rowid & (NL - 1);
    const int cntM  = which ? g_cntB[bb] : g_cntA[bb];
    const int cntK  = which ? g_cntA[bb] : g_cntB[bb];
    if (r >= cntM) return;
    const float* Srow = (which ? g_ST : g_S) + (size_t)rowid * NL;
    float* oMax = which ? g_colMax : g_rowMax;
    float* oSc  = which ? g_colScale : g_rowScale;

    const int k4 = cntK & ~3;
    float m = -INFINITY;
    for (int j = lane * 4; j < k4; j += 128) {
        float4 v = *(const float4*)(Srow + j);
        m = fmaxf(m, fmaxf(fmaxf(v.x, v.y), fmaxf(v.z, v.w)));
    }
    for (int j = k4 + lane; j < cntK; j += 32) m = fmaxf(m, Srow[j]);
#pragma unroll
    for (int o = 16; o > 0; o >>= 1) m = fmaxf(m, __shfl_xor_sync(0xffffffffu, m, o));

    float s = 0.f;
    if (m != -INFINITY) {
        for (int j = lane * 4; j < k4; j += 128) {
            float4 v = *(const float4*)(Srow + j);
            s += __expf(v.x - m) + __expf(v.y - m) + __expf(v.z - m) + __expf(v.w - m);
        }
        for (int j = k4 + lane; j < cntK; j += 32) s += __expf(Srow[j] - m);
    }
#pragma unroll
    for (int o = 16; o > 0; o >>= 1) s += __shfl_xor_sync(0xffffffffu, s, o);

    if (lane == 0) {
        if (m == -INFINITY) { oMax[rowid] = 0.f; oSc[rowid] = 0.f; }
        else                { oMax[rowid] = m;   oSc[rowid] = 1.f / s; }
    }
}

// ---------------------------------------------------------------------------
// K3 (R10/R11 version): attended = softmax-weights @ values; both directions.
// K=16 half-chunk double buffer (static 48KB): stage = [Wh|Wl|Vh|Vl].
// W from 1-row-per-thread S prefetch; stats in registers.
// ---------------------------------------------------------------------------
__global__ void __launch_bounds__(256, 2) k3_mma(float* __restrict__ outA,
                                                 float* __restrict__ outB) {
    const int z     = blockIdx.z;
    const int which = z >> 5;
    const int bb    = z & 31;
    const int m0    = blockIdx.y * 128;
    const int db0   = blockIdx.x * 128;
    const int cntM  = which ? g_cntB[bb] : g_cntA[bb];
    const int cntK  = which ? g_cntA[bb] : g_cntB[bb];
    if (m0 >= cntM) return;
    float* out = which ? outB : outA;

    const float* Sarr = which ? g_ST : g_S;
    const float* stM  = which ? g_colMax : g_rowMax;
    const float* stSc = which ? g_colScale : g_rowScale;
    const __nv_bfloat16* VhT = which ? g_AhiT : g_BhiT;
    const __nv_bfloat16* VlT = which ? g_AloT : g_BloT;
    const int* idxOut = (which ? g_idxB : g_idxA) + bb * NL;

    __shared__ __align__(16) __nv_bfloat16 smh[2 * 4 * HARR];  // 49152 B
    const uint32_t base_u = smem_u32(smh);

    const int t    = threadIdx.x;
    const int lane = t & 31;
    const int wid  = t >> 5;
    const int wm   = wid >> 1;
    const int wn   = wid & 1;
    const int gq   = lane >> 2;

    const int lrow = (lane & 7) + ((lane >> 3) & 1) * 8;
    const int lcol = (lane >> 4) * 8;

    const int wrow = t >> 1;
    const int wcol = (t & 1) * 8;
    const float mreg = stM[bb * NL + m0 + wrow];

    const int er = wm * 32 + gq;
    const float esc0 = stSc[bb * NL + m0 + er];
    const float esc1 = stSc[bb * NL + m0 + er + 8];
    const float esc2 = stSc[bb * NL + m0 + er + 16];
    const float esc3 = stSc[bb * NL + m0 + er + 24];
    const int eid0 = idxOut[m0 + er];
    const int eid1 = idxOut[m0 + er + 8];
    const int eid2 = idxOut[m0 + er + 16];
    const int eid3 = idxOut[m0 + er + 24];

    float c[2][8][4];
#pragma unroll
    for (int mf = 0; mf < 2; mf++)
#pragma unroll
        for (int nf = 0; nf < 8; nf++)
#pragma unroll
            for (int v = 0; v < 4; v++) c[mf][nf][v] = 0.f;

    const size_t sBase = ((size_t)bb * NL + m0) * NL;
    const size_t vBase = ((size_t)bb * ND + db0) * NL;
    const int nch = ((cntK + 15) & ~15) / 16;
    const int cprow = t >> 1;
    const int cpc8  = (t & 1) * 8;

    auto issueV = [&](int ci, int s) {
        const uint32_t st = base_u + (uint32_t)s * HSTAGE + 2 * HARRB;
        size_t go = vBase + (size_t)cprow * NL + ci * 16 + cpc8;
        uint32_t so = st + (uint32_t)((cprow * RS2 + cpc8) * 2);
        cpasync16(so,         &VhT[go]);
        cpasync16(so + HARRB, &VlT[go]);
        cpasync_commit();
    };

    float4 s0, s1;
    auto loadS = [&](int ci) {
        const float* p = &Sarr[sBase + (size_t)wrow * NL + ci * 16 + wcol];
        s0 = *(const float4*)p;
        s1 = *(const float4*)(p + 4);
    };
    auto storeW = [&](int ci, int s) {
        __nv_bfloat16* sWh = smh + s * (4 * HARR);
        __nv_bfloat16* sWl = sWh + HARR;
        int cb = ci * 16 + wcol;
        float w0 = (cb + 0 < cntK) ? __expf(s0.x - mreg) : 0.f;
        float w1 = (cb + 1 < cntK) ? __expf(s0.y - mreg) : 0.f;
        float w2 = (cb + 2 < cntK) ? __expf(s0.z - mreg) : 0.f;
        float w3 = (cb + 3 < cntK) ? __expf(s0.w - mreg) : 0.f;
        float w4 = (cb + 4 < cntK) ? __expf(s1.x - mreg) : 0.f;
        float w5 = (cb + 5 < cntK) ? __expf(s1.y - mreg) : 0.f;
        float w6 = (cb + 6 < cntK) ? __expf(s1.z - mreg) : 0.f;
        float w7 = (cb + 7 < cntK) ? __expf(s1.w - mreg) : 0.f;
        __nv_bfloat162 h01 = __floats2bfloat162_rn(w0, w1);
        __nv_bfloat162 h23 = __floats2bfloat162_rn(w2, w3);
        __nv_bfloat162 h45 = __floats2bfloat162_rn(w4, w5);
        __nv_bfloat162 h67 = __floats2bfloat162_rn(w6, w7);
        __nv_bfloat162 l01 = __floats2bfloat162_rn(
            w0 - __bfloat162float(__low2bfloat16(h01)),
            w1 - __bfloat162float(__high2bfloat16(h01)));
        __nv_bfloat162 l23 = __floats2bfloat162_rn(
            w2 - __bfloat162float(__low2bfloat16(h23)),
            w3 - __bfloat162float(__high2bfloat16(h23)));
        __nv_bfloat162 l45 = __floats2bfloat162_rn(
            w4 - __bfloat162float(__low2bfloat16(h45)),
            w5 - __bfloat162float(__high2bfloat16(h45)));
        __nv_bfloat162 l67 = __floats2bfloat162_rn(
            w6 - __bfloat162float(__low2bfloat16(h67)),
            w7 - __bfloat162float(__high2bfloat16(h67)));
        int so = wrow * RS2 + wcol;
        *(uint4*)&sWh[so] = make_uint4(bf2_as_u32(h01), bf2_as_u32(h23),
                                       bf2_as_u32(h45), bf2_as_u32(h67));
        *(uint4*)&sWl[so] = make_uint4(bf2_as_u32(l01), bf2_as_u32(l23),
                                       bf2_as_u32(l45), bf2_as_u32(l67));
    };

    // prologue
    issueV(0, 0);
    if (nch > 1) issueV(1, 1);
    loadS(0);
    storeW(0, 0);

#pragma unroll 1
    for (int i = 0; i < nch; i++) {
        if (i == nch - 1) cpasync_wait0(); else cpasync_wait1();
        __syncthreads();
        const bool more = (i + 1 < nch);
        if (more) loadS(i + 1);  // 8 regs, LDG in flight under the MMAs
        const uint32_t st = base_u + (uint32_t)(i & 1) * HSTAGE;
#pragma unroll
        for (int term = 0; term < 3; term++) {
            const uint32_t au = st + ((term == 2) ? HARRB : 0u);
            const uint32_t bu = st + 2 * HARRB + ((term == 1) ? HARRB : 0u);
            uint32_t b0[8], b1[8];
#pragma unroll
            for (int nfp = 0; nfp < 4; nfp++) {
                uint32_t addr = bu +
                    (uint32_t)(((wn * 64 + nfp * 16 + lrow) * RS2 + lcol) * 2);
                ldsm_x4(b0[2 * nfp], b0[2 * nfp + 1], b1[2 * nfp], b1[2 * nfp + 1], addr);
            }
#pragma unroll
            for (int mf = 0; mf < 2; mf++) {
                uint32_t a0, a1, a2, a3;
                uint32_t addrA = au +
                    (uint32_t)(((wm * 32 + mf * 16 + lrow) * RS2 + lcol) * 2);
                ldsm_x4(a0, a1, a2, a3, addrA);
#pragma unroll
                for (int nf = 0; nf < 8; nf++)
                    mma_bf16(c[mf][nf], a0, a1, a2, a3, b0[nf], b1[nf]);
            }
        }
        __syncthreads();
        if (more) storeW(i + 1, (i + 1) & 1);
        if (i + 2 < nch) issueV(i + 2, i & 1);
    }

    // ---- epilogue: scale + scatter (stats from registers)
#pragma unroll
    for (int mf = 0; mf < 2; mf++) {
        int rl = wm * 32 + mf * 16 + gq;
        float scA = mf ? esc2 : esc0;
        float scB = mf ? esc3 : esc1;
        int   idA = mf ? eid2 : eid0;
        int   idB = mf ? eid3 : eid1;
#pragma unroll
        for (int nf = 0; nf < 8; nf++) {
            int jj = db0 + wn * 64 + nf * 8 + 2 * (lane & 3);
            if (m0 + rl < cntM) {
                *(float2*)&out[((size_t)(bb * NL) + idA) * ND + jj] =
                    make_float2(c[mf][nf][0] * scA, c[mf][nf][1] * scA);
            }
            if (m0 + rl + 8 < cntM) {
                *(float2*)&out[((size_t)(bb * NL) + idB) * ND + jj] =
                    make_float2(c[mf][nf][2] * scB, c[mf][nf][3] * scB);
            }
        }
    }
}

// ---------------------------------------------------------------------------
extern "C" void kernel_launch(void* const* d_in, const int* in_sizes, int n_in,
                              void* d_out, int out_size) {
    const float* a      = (const float*)d_in[0];
    const float* b      = (const float*)d_in[1];
    const int*   mask_a = (const int*)d_in[2];
    const int*   mask_b = (const int*)d_in[3];
    float* outA = (float*)d_out;
    float* outB = outA + (size_t)NB * NL * ND;

    k0_compact<<<64, 1024>>>(mask_a, mask_b);
    k_zero<<<dim3(NL / 8, NB, 2), 256>>>(mask_a, mask_b, outA, outB);
    k_conv<<<dim3(8, 32, 64), 256>>>(a, b);
    k1_mma<<<dim3(8, 8, NB), 256>>>();
    k2_stats<<<dim3(NB * NL / 8, 2), 256>>>();
    k3_mma<<<dim3(2, 8, 64), 256>>>(outA, outB);
}

// round 17
// speedup vs baseline: 1.4480x; 1.1116x over previous
#include <cuda_runtime.h>
#include <cuda_bf16.h>
#include <cuda_fp16.h>
#include <math.h>
#include <cstdint>

// Problem constants
constexpr int NB = 32;    // batch
constexpr int NL = 1024;  // La = Lb
constexpr int ND = 256;   // feature dim

// Scratch
__device__ float g_S [(size_t)NB * NL * NL];   // logits, compact [i][j]
__device__ float g_ST[(size_t)NB * NL * NL];   // logits transposed, compact [j][i]
__device__ float g_rowMax[NB * NL];
__device__ float g_rowScale[NB * NL];
__device__ float g_colMax[NB * NL];
__device__ float g_colScale[NB * NL];
__device__ int   g_idxA[NB * NL];
__device__ int   g_idxB[NB * NL];
__device__ int   g_cntA[NB];
__device__ int   g_cntB[NB];

// Compacted bf16 hi/lo copies of a, b (row = compact position) — for k1.
__device__ __nv_bfloat16 g_Ahi [(size_t)NB * NL * ND];
__device__ __nv_bfloat16 g_Alo [(size_t)NB * NL * ND];
__device__ __nv_bfloat16 g_Bhi [(size_t)NB * NL * ND];
__device__ __nv_bfloat16 g_Blo [(size_t)NB * NL * ND];
// Transposed fp16 hi/lo copies [d][compact] — for k3 (f16 MMA path).
__device__ __half g_AhT[(size_t)NB * ND * NL];
__device__ __half g_AlT[(size_t)NB * ND * NL];
__device__ __half g_BhT[(size_t)NB * ND * NL];
__device__ __half g_BlT[(size_t)NB * ND * NL];

// k1 geometry: K=32 chunks, rows of 40 bf16 (80B), single buffer.
constexpr int RS = 40;
// k3 geometry: K=16 half-chunks, rows of 24 halves (48B), double buffer.
constexpr int RS2  = 24;
constexpr int HARR = 128 * RS2;          // 3072 elems
constexpr uint32_t HARRB   = HARR * 2;   // 6144 B
constexpr uint32_t HSTAGE3 = 3 * HARRB;  // 18432 B per stage (Wf|Vh|Vl)

// m16n8k16 bf16 MMA, fp32 accumulate
__device__ __forceinline__ void mma_bf16(float* c, uint32_t a0, uint32_t a1,
                                         uint32_t a2, uint32_t a3,
                                         uint32_t b0, uint32_t b1) {
    asm volatile(
        "mma.sync.aligned.m16n8k16.row.col.f32.bf16.bf16.f32 "
        "{%0,%1,%2,%3}, {%4,%5,%6,%7}, {%8,%9}, {%0,%1,%2,%3};"
        : "+f"(c[0]), "+f"(c[1]), "+f"(c[2]), "+f"(c[3])
        : "r"(a0), "r"(a1), "r"(a2), "r"(a3), "r"(b0), "r"(b1));
}

// m16n8k16 fp16 MMA, fp32 accumulate
__device__ __forceinline__ void mma_f16(float* c, uint32_t a0, uint32_t a1,
                                        uint32_t a2, uint32_t a3,
                                        uint32_t b0, uint32_t b1) {
    asm volatile(
        "mma.sync.aligned.m16n8k16.row.col.f32.f16.f16.f32 "
        "{%0,%1,%2,%3}, {%4,%5,%6,%7}, {%8,%9}, {%0,%1,%2,%3};"
        : "+f"(c[0]), "+f"(c[1]), "+f"(c[2]), "+f"(c[3])
        : "r"(a0), "r"(a1), "r"(a2), "r"(a3), "r"(b0), "r"(b1));
}

__device__ __forceinline__ void ldsm_x4(uint32_t& r0, uint32_t& r1,
                                        uint32_t& r2, uint32_t& r3, uint32_t addr) {
    asm volatile("ldmatrix.sync.aligned.m8n8.x4.shared.b16 {%0,%1,%2,%3}, [%4];"
        : "=r"(r0), "=r"(r1), "=r"(r2), "=r"(r3) : "r"(addr));
}

__device__ __forceinline__ uint32_t smem_u32(const void* p) {
    uint32_t a;
    asm("{ .reg .u64 tmp; cvta.to.shared.u64 tmp, %1; cvt.u32.u64 %0, tmp; }"
        : "=r"(a) : "l"(p));
    return a;
}

__device__ __forceinline__ void cpasync16(uint32_t saddr, const void* gptr) {
    asm volatile("cp.async.cg.shared.global [%0], [%1], 16;"
        :: "r"(saddr), "l"(gptr) : "memory");
}
__device__ __forceinline__ void cpasync_commit() {
    asm volatile("cp.async.commit_group;" ::: "memory");
}
__device__ __forceinline__ void cpasync_wait0() {
    asm volatile("cp.async.wait_group 0;" ::: "memory");
}
__device__ __forceinline__ void cpasync_wait1() {
    asm volatile("cp.async.wait_group 1;" ::: "memory");
}

__device__ __forceinline__ uint32_t h2_as_u32(__half2 v) {
    return *(uint32_t*)&v;
}

// ---------------------------------------------------------------------------
// K0: per-batch mask compaction (idx padded to 1024 with last valid index).
// ---------------------------------------------------------------------------
__global__ void __launch_bounds__(1024) k0_compact(const int* __restrict__ mask_a,
                                                   const int* __restrict__ mask_b) {
    const int which = blockIdx.x >> 5;
    const int bb    = blockIdx.x & 31;
    const int* m = (which ? mask_b : mask_a) + bb * NL;
    int* idx = (which ? g_idxB : g_idxA) + bb * NL;
    int* cnt = which ? g_cntB : g_cntA;
    const int t = threadIdx.x, lane = t & 31, w = t >> 5;

    int mv = (m[t] != 0);
    unsigned bal = __ballot_sync(0xffffffffu, mv);
    int pw = __popc(bal & ((1u << lane) - 1));
    __shared__ int wc[32];
    if (lane == 0) wc[w] = __popc(bal);
    __syncthreads();
    if (t < 32) {
        int v = wc[t];
#pragma unroll
        for (int o = 1; o < 32; o <<= 1) {
            int u = __shfl_up_sync(0xffffffffu, v, o);
            if (lane >= o) v += u;
        }
        wc[t] = v;
    }
    __syncthreads();
    const int base  = (w == 0) ? 0 : wc[w - 1];
    const int total = wc[31];
    if (mv) idx[base + pw] = t;
    if (t == 0) cnt[bb] = total;
    __syncthreads();
    __shared__ int lastIdx;
    if (t == 0) lastIdx = (total > 0) ? idx[total - 1] : 0;
    __syncthreads();
    if (t >= total) idx[t] = lastIdx;
}

// ---------------------------------------------------------------------------
// KZ: zero only masked output rows (replaces full memset).
// ---------------------------------------------------------------------------
__global__ void __launch_bounds__(256) k_zero(const int* __restrict__ mask_a,
                                              const int* __restrict__ mask_b,
                                              float* __restrict__ outA,
                                              float* __restrict__ outB) {
    const int which = blockIdx.z;
    const int bb    = blockIdx.y;
    const int row   = blockIdx.x * 8 + (threadIdx.x >> 5);
    const int lane  = threadIdx.x & 31;
    const int* m = which ? mask_b : mask_a;
    float* out   = which ? outB : outA;
    if (m[bb * NL + row] == 0) {
        float4 z = make_float4(0.f, 0.f, 0.f, 0.f);
        float* p = out + ((size_t)bb * NL + row) * ND;
        *(float4*)(p + lane * 4)       = z;
        *(float4*)(p + 128 + lane * 4) = z;
    }
}

// ---------------------------------------------------------------------------
// KC: gather-compact; bf16 hi/lo non-transposed (k1) + fp16 hi/lo transposed (k3).
// ---------------------------------------------------------------------------
__global__ void __launch_bounds__(256) k_conv(const float* __restrict__ a,
                                              const float* __restrict__ b) {
    const int z     = blockIdx.z;
    const int which = z >> 5;               // 0: a, 1: b
    const int bb    = z & 31;
    const int dt    = blockIdx.x * 32;
    const int rt    = blockIdx.y * 32;
    const int cnt   = which ? g_cntB[bb] : g_cntA[bb];
    if (rt >= ((cnt + 127) & ~127)) return;
    const float* src = which ? b : a;
    const int* idx   = (which ? g_idxB : g_idxA) + bb * NL;
    __nv_bfloat16* oH = which ? g_Bhi : g_Ahi;
    __nv_bfloat16* oL = which ? g_Blo : g_Alo;
    __half* oHT = which ? g_BhT : g_AhT;
    __half* oLT = which ? g_BlT : g_AlT;

    const int tx = threadIdx.x & 31;
    const int ty = threadIdx.x >> 5;
    __shared__ float tile[32][33];

#pragma unroll
    for (int rr = 0; rr < 4; rr++) {
        int rl = ty + 8 * rr;
        int grow = idx[rt + rl];
        float v = src[((size_t)bb * NL + grow) * ND + dt + tx];
        tile[rl][tx] = v;
        __nv_bfloat16 h = __float2bfloat16(v);
        __nv_bfloat16 l = __float2bfloat16(v - __bfloat162float(h));
        size_t o = ((size_t)bb * NL + rt + rl) * ND + dt + tx;
        oH[o] = h; oL[o] = l;
    }
    __syncthreads();
#pragma unroll
    for (int rr = 0; rr < 4; rr++) {
        int dl = ty + 8 * rr;
        float v = tile[tx][dl];
        __half h = __float2half_rn(v);
        __half l = __float2half_rn(v - __half2float(h));
        size_t o = ((size_t)bb * ND + dt + dl) * NL + rt + tx;
        oHT[o] = h; oLT[o] = l;
    }
}

// ---------------------------------------------------------------------------
// K1 (R15 version): S = a_c @ b_c^T, 3-term bf16 mma.sync, ldmatrix,
// K=32 chunks, single buffer + cp.async. Writes g_S AND g_ST (2-pass transpose).
// ---------------------------------------------------------------------------
__global__ void __launch_bounds__(256, 2) k1_mma() {
    const int bb  = blockIdx.z;
    const int ib0 = blockIdx.y * 128;
    const int jb0 = blockIdx.x * 128;
    const int na  = g_cntA[bb];
    const int nb  = g_cntB[bb];
    if (ib0 >= na || jb0 >= nb) return;

    __shared__ __align__(16) __nv_bfloat16 sm[4 * 128 * RS];  // 40960B
    __nv_bfloat16* sAh = sm;
    __nv_bfloat16* sAl = sAh + 128 * RS;
    __nv_bfloat16* sBh = sAl + 128 * RS;
    __nv_bfloat16* sBl = sBh + 128 * RS;
    float* tbuf = (float*)sm;  // reused post-MMA (64*132*4 = 33792 <= 40960)

    const int t    = threadIdx.x;
    const int lane = t & 31;
    const int wid  = t >> 5;
    const int wm   = wid >> 1;   // 0..3
    const int wn   = wid & 1;    // 0..1
    const int gq   = lane >> 2;

    const int lrow = (lane & 7) + ((lane >> 3) & 1) * 8;
    const int lcol = (lane >> 4) * 8;

    const uint32_t sAh_u = smem_u32(sAh), sAl_u = smem_u32(sAl);
    const uint32_t sBh_u = smem_u32(sBh), sBl_u = smem_u32(sBl);

    float c[2][8][4];
#pragma unroll
    for (int mf = 0; mf < 2; mf++)
#pragma unroll
        for (int nf = 0; nf < 8; nf++)
#pragma unroll
            for (int v = 0; v < 4; v++) c[mf][nf][v] = 0.f;

    const size_t aBase = ((size_t)bb * NL + ib0) * ND;
    const size_t bBase = ((size_t)bb * NL + jb0) * ND;
    const int cprow0 = t >> 2;          // +64 per pass
    const int cpc8   = (t & 3) * 8;     // bf16 col (8 per 16B)

    // issue chunk 0
#pragma unroll
    for (int p = 0; p < 2; p++) {
        int row = cprow0 + 64 * p;
        size_t go = (size_t)row * ND + cpc8;
        uint32_t so = (uint32_t)((row * RS + cpc8) * 2);
        cpasync16(sAh_u + so, &g_Ahi[aBase + go]);
        cpasync16(sAl_u + so, &g_Alo[aBase + go]);
        cpasync16(sBh_u + so, &g_Bhi[bBase + go]);
        cpasync16(sBl_u + so, &g_Blo[bBase + go]);
    }
    cpasync_commit();

#pragma unroll 1
    for (int kc = 0; kc < ND; kc += 32) {
        cpasync_wait0();
        __syncthreads();
#pragma unroll
        for (int term = 0; term < 3; term++) {
            const uint32_t au = (term == 2) ? sAl_u : sAh_u;
            const uint32_t bu = (term == 1) ? sBl_u : sBh_u;
#pragma unroll
            for (int k0 = 0; k0 < 32; k0 += 16) {
                uint32_t b0[8], b1[8];
#pragma unroll
                for (int nfp = 0; nfp < 4; nfp++) {
                    uint32_t addr = bu +
                        (uint32_t)(((wn * 64 + nfp * 16 + lrow) * RS + k0 + lcol) * 2);
                    ldsm_x4(b0[2 * nfp], b0[2 * nfp + 1], b1[2 * nfp], b1[2 * nfp + 1], addr);
                }
#pragma unroll
                for (int mf = 0; mf < 2; mf++) {
                    uint32_t a0, a1, a2, a3;
                    uint32_t addrA = au +
                        (uint32_t)(((wm * 32 + mf * 16 + lrow) * RS + k0 + lcol) * 2);
                    ldsm_x4(a0, a1, a2, a3, addrA);
#pragma unroll
                    for (int nf = 0; nf < 8; nf++)
                        mma_bf16(c[mf][nf], a0, a1, a2, a3, b0[nf], b1[nf]);
                }
            }
        }
        __syncthreads();
        if (kc + 32 < ND) {
#pragma unroll
            for (int p = 0; p < 2; p++) {
                int row = cprow0 + 64 * p;
                size_t go = (size_t)row * ND + kc + 32 + cpc8;
                uint32_t so = (uint32_t)((row * RS + cpc8) * 2);
                cpasync16(sAh_u + so, &g_Ahi[aBase + go]);
                cpasync16(sAl_u + so, &g_Alo[aBase + go]);
                cpasync16(sBh_u + so, &g_Bhi[bBase + go]);
                cpasync16(sBl_u + so, &g_Blo[bBase + go]);
            }
            cpasync_commit();
        }
    }

    // ---- epilogue 1: direct store to g_S
#pragma unroll
    for (int mf = 0; mf < 2; mf++)
#pragma unroll
        for (int nf = 0; nf < 8; nf++) {
            int r  = ib0 + wm * 32 + mf * 16 + gq;
            int jj = jb0 + wn * 64 + nf * 8 + 2 * (lane & 3);
            *(float2*)&g_S[((size_t)(bb * NL) + r) * NL + jj] =
                make_float2(c[mf][nf][0], c[mf][nf][1]);
            *(float2*)&g_S[((size_t)(bb * NL) + r + 8) * NL + jj] =
                make_float2(c[mf][nf][2], c[mf][nf][3]);
        }

    // ---- epilogue 2: transpose to g_ST via smem, 2 passes of 64 j-cols
#pragma unroll 1
    for (int p = 0; p < 2; p++) {
        __syncthreads();
        if (wn == p) {
#pragma unroll
            for (int mf = 0; mf < 2; mf++)
#pragma unroll
                for (int nf = 0; nf < 8; nf++) {
                    int jl = nf * 8 + 2 * (lane & 3);        // 0..63 within pass
                    int il = wm * 32 + mf * 16 + gq;
                    tbuf[jl * 132 + il]           = c[mf][nf][0];
                    tbuf[(jl + 1) * 132 + il]     = c[mf][nf][1];
                    tbuf[jl * 132 + il + 8]       = c[mf][nf][2];
                    tbuf[(jl + 1) * 132 + il + 8] = c[mf][nf][3];
                }
        }
        __syncthreads();
#pragma unroll
        for (int q = 0; q < 8; q++) {
            int id  = t + 256 * q;      // 0..2047: 64 j-rows x 32 float4
            int jl  = id >> 5;
            int il4 = (id & 31) * 4;
            int gj  = jb0 + p * 64 + jl;
            *(float4*)&g_ST[((size_t)(bb * NL) + gj) * NL + ib0 + il4] =
                *(float4*)&tbuf[jl * 132 + il4];
        }
    }
}

// ---------------------------------------------------------------------------
// K2: softmax stats; both orientations in ONE launch (which = blockIdx.y).
// ---------------------------------------------------------------------------
__global__ void __launch_bounds__(256) k2_stats() {
    const int which = blockIdx.y;
    const int warp  = threadIdx.x >> 5;
    const int lane  = threadIdx.x & 31;
    const int rowid = blockIdx.x * 8 + warp;
    const int bb    = rowid >> 10;
    const int r     = rowid & (NL - 1);
    const int cntM  = which ? g_cntB[bb] : g_cntA[bb];
    const int cntK  = which ? g_cntA[bb] : g_cntB[bb];
    if (r >= cntM) return;
    const float* Srow = (which ? g_ST : g_S) + (size_t)rowid * NL;
    float* oMax = which ? g_colMax : g_rowMax;
    float* oSc  = which ? g_colScale : g_rowScale;

    const int k4 = cntK & ~3;
    float m = -INFINITY;
    for (int j = lane * 4; j < k4; j += 128) {
        float4 v = *(const float4*)(Srow + j);
        m = fmaxf(m, fmaxf(fmaxf(v.x, v.y), fmaxf(v.z, v.w)));
    }
    for (int j = k4 + lane; j < cntK; j += 32) m = fmaxf(m, Srow[j]);
#pragma unroll
    for (int o = 16; o > 0; o >>= 1) m = fmaxf(m, __shfl_xor_sync(0xffffffffu, m, o));

    float s = 0.f;
    if (m != -INFINITY) {
        for (int j = lane * 4; j < k4; j += 128) {
            float4 v = *(const float4*)(Srow + j);
            s += __expf(v.x - m) + __expf(v.y - m) + __expf(v.z - m) + __expf(v.w - m);
        }
        for (int j = k4 + lane; j < cntK; j += 32) s += __expf(Srow[j] - m);
    }
#pragma unroll
    for (int o = 16; o > 0; o >>= 1) s += __shfl_xor_sync(0xffffffffu, s, o);

    if (lane == 0) {
        if (m == -INFINITY) { oMax[rowid] = 0.f; oSc[rowid] = 0.f; }
        else                { oMax[rowid] = m;   oSc[rowid] = 1.f / s; }
    }
}

// ---------------------------------------------------------------------------
// K3 (fp16, 2-term): attended = softmax-weights @ values; both directions.
// K=16 half-chunk double buffer (36KB static): stage = [Wf | Vh | Vl] fp16.
// W = exp(S-M) single fp16 term; V fp16 hi/lo. A-frags loaded once per chunk.
// ---------------------------------------------------------------------------
__global__ void __launch_bounds__(256, 2) k3_mma(float* __restrict__ outA,
                                                 float* __restrict__ outB) {
    const int z     = blockIdx.z;
    const int which = z >> 5;
    const int bb    = z & 31;
    const int m0    = blockIdx.y * 128;
    const int db0   = blockIdx.x * 128;
    const int cntM  = which ? g_cntB[bb] : g_cntA[bb];
    const int cntK  = which ? g_cntA[bb] : g_cntB[bb];
    if (m0 >= cntM) return;
    float* out = which ? outB : outA;

    const float* Sarr = which ? g_ST : g_S;
    const float* stM  = which ? g_colMax : g_rowMax;
    const float* stSc = which ? g_colScale : g_rowScale;
    const __half* VhT = which ? g_AhT : g_BhT;
    const __half* VlT = which ? g_AlT : g_BlT;
    const int* idxOut = (which ? g_idxB : g_idxA) + bb * NL;

    __shared__ __align__(16) __half smh[2 * 3 * HARR];  // 36864 B
    const uint32_t base_u = smem_u32(smh);

    const int t    = threadIdx.x;
    const int lane = t & 31;
    const int wid  = t >> 5;
    const int wm   = wid >> 1;
    const int wn   = wid & 1;
    const int gq   = lane >> 2;

    const int lrow = (lane & 7) + ((lane >> 3) & 1) * 8;
    const int lcol = (lane >> 4) * 8;

    const int wrow = t >> 1;
    const int wcol = (t & 1) * 8;
    const float mreg = stM[bb * NL + m0 + wrow];

    const int er = wm * 32 + gq;
    const float esc0 = stSc[bb * NL + m0 + er];
    const float esc1 = stSc[bb * NL + m0 + er + 8];
    const float esc2 = stSc[bb * NL + m0 + er + 16];
    const float esc3 = stSc[bb * NL + m0 + er + 24];
    const int eid0 = idxOut[m0 + er];
    const int eid1 = idxOut[m0 + er + 8];
    const int eid2 = idxOut[m0 + er + 16];
    const int eid3 = idxOut[m0 + er + 24];

    float c[2][8][4];
#pragma unroll
    for (int mf = 0; mf < 2; mf++)
#pragma unroll
        for (int nf = 0; nf < 8; nf++)
#pragma unroll
            for (int v = 0; v < 4; v++) c[mf][nf][v] = 0.f;

    const size_t sBase = ((size_t)bb * NL + m0) * NL;
    const size_t vBase = ((size_t)bb * ND + db0) * NL;
    const int nch = ((cntK + 15) & ~15) / 16;
    const int cprow = t >> 1;
    const int cpc8  = (t & 1) * 8;

    auto issueV = [&](int ci, int s) {
        const uint32_t st = base_u + (uint32_t)s * HSTAGE3 + HARRB;  // Vh slot
        size_t go = vBase + (size_t)cprow * NL + ci * 16 + cpc8;
        uint32_t so = st + (uint32_t)((cprow * RS2 + cpc8) * 2);
        cpasync16(so,         &VhT[go]);
        cpasync16(so + HARRB, &VlT[go]);
        cpasync_commit();
    };

    float4 s0, s1;
    auto loadS = [&](int ci) {
        const float* p = &Sarr[sBase + (size_t)wrow * NL + ci * 16 + wcol];
        s0 = *(const float4*)p;
        s1 = *(const float4*)(p + 4);
    };
    auto storeW = [&](int ci, int s) {
        __half* sW = smh + s * (3 * HARR);
        int cb = ci * 16 + wcol;
        float w0 = (cb + 0 < cntK) ? __expf(s0.x - mreg) : 0.f;
        float w1 = (cb + 1 < cntK) ? __expf(s0.y - mreg) : 0.f;
        float w2 = (cb + 2 < cntK) ? __expf(s0.z - mreg) : 0.f;
        float w3 = (cb + 3 < cntK) ? __expf(s0.w - mreg) : 0.f;
        float w4 = (cb + 4 < cntK) ? __expf(s1.x - mreg) : 0.f;
        float w5 = (cb + 5 < cntK) ? __expf(s1.y - mreg) : 0.f;
        float w6 = (cb + 6 < cntK) ? __expf(s1.z - mreg) : 0.f;
        float w7 = (cb + 7 < cntK) ? __expf(s1.w - mreg) : 0.f;
        __half2 p01 = __floats2half2_rn(w0, w1);
        __half2 p23 = __floats2half2_rn(w2, w3);
        __half2 p45 = __floats2half2_rn(w4, w5);
        __half2 p67 = __floats2half2_rn(w6, w7);
        int so = wrow * RS2 + wcol;
        *(uint4*)&sW[so] = make_uint4(h2_as_u32(p01), h2_as_u32(p23),
                                      h2_as_u32(p45), h2_as_u32(p67));
    };

    // prologue
    issueV(0, 0);
    if (nch > 1) issueV(1, 1);
    loadS(0);
    storeW(0, 0);

#pragma unroll 1
    for (int i = 0; i < nch; i++) {
        if (i == nch - 1) cpasync_wait0(); else cpasync_wait1();
        __syncthreads();
        const bool more = (i + 1 < nch);
        if (more) loadS(i + 1);  // 8 regs, LDG in flight under the MMAs
        const uint32_t st = base_u + (uint32_t)(i & 1) * HSTAGE3;

        // A-fragments (W) loaded once, shared across both terms
        uint32_t a[2][4];
#pragma unroll
        for (int mf = 0; mf < 2; mf++) {
            uint32_t addrA = st +
                (uint32_t)(((wm * 32 + mf * 16 + lrow) * RS2 + lcol) * 2);
            ldsm_x4(a[mf][0], a[mf][1], a[mf][2], a[mf][3], addrA);
        }
#pragma unroll
        for (int term = 0; term < 2; term++) {
            const uint32_t bu = st + HARRB + (uint32_t)term * HARRB;
            uint32_t b0[8], b1[8];
#pragma unroll
            for (int nfp = 0; nfp < 4; nfp++) {
                uint32_t addr = bu +
                    (uint32_t)(((wn * 64 + nfp * 16 + lrow) * RS2 + lcol) * 2);
                ldsm_x4(b0[2 * nfp], b0[2 * nfp + 1], b1[2 * nfp], b1[2 * nfp + 1], addr);
            }
#pragma unroll
            for (int mf = 0; mf < 2; mf++)
#pragma unroll
                for (int nf = 0; nf < 8; nf++)
                    mma_f16(c[mf][nf], a[mf][0], a[mf][1], a[mf][2], a[mf][3],
                            b0[nf], b1[nf]);
        }
        __syncthreads();
        if (more) storeW(i + 1, (i + 1) & 1);
        if (i + 2 < nch) issueV(i + 2, i & 1);
    }

    // ---- epilogue: scale + scatter (stats from registers)
#pragma unroll
    for (int mf = 0; mf < 2; mf++) {
        int rl = wm * 32 + mf * 16 + gq;
        float scA = mf ? esc2 : esc0;
        float scB = mf ? esc3 : esc1;
        int   idA = mf ? eid2 : eid0;
        int   idB = mf ? eid3 : eid1;
#pragma unroll
        for (int nf = 0; nf < 8; nf++) {
            int jj = db0 + wn * 64 + nf * 8 + 2 * (lane & 3);
            if (m0 + rl < cntM) {
                *(float2*)&out[((size_t)(bb * NL) + idA) * ND + jj] =
                    make_float2(c[mf][nf][0] * scA, c[mf][nf][1] * scA);
            }
            if (m0 + rl + 8 < cntM) {
                *(float2*)&out[((size_t)(bb * NL) + idB) * ND + jj] =
                    make_float2(c[mf][nf][2] * scB, c[mf][nf][3] * scB);
            }
        }
    }
}

// ---------------------------------------------------------------------------
extern "C" void kernel_launch(void* const* d_in, const int* in_sizes, int n_in,
                              void* d_out, int out_size) {
    const float* a      = (const float*)d_in[0];
    const float* b      = (const float*)d_in[1];
    const int*   mask_a = (const int*)d_in[2];
    const int*   mask_b = (const int*)d_in[3];
    float* outA = (float*)d_out;
    float* outB = outA + (size_t)NB * NL * ND;

    k0_compact<<<64, 1024>>>(mask_a, mask_b);
    k_zero<<<dim3(NL / 8, NB, 2), 256>>>(mask_a, mask_b, outA, outB);
    k_conv<<<dim3(8, 32, 64), 256>>>(a, b);
    k1_mma<<<dim3(8, 8, NB), 256>>>();
    k2_stats<<<dim3(NB * NL / 8, 2), 256>>>();
    k3_mma<<<dim3(2, 8, 64), 256>>>(outA, outB);
}